// round 12
// baseline (speedup 1.0000x reference)
#include <cuda_runtime.h>
#include <cuda_bf16.h>
#include <math.h>
#include <stdint.h>

#define Ln 128
#define Bn 4096
#define Dn 300
#define KP2 304                 // K padded: 19 steps of 16
#define XROW 624                // 304 bf16 + 16B pad
#define SM_X  0
#define SM_RA 79872             // 128*624
#define SM_RC 80896
#define DYN_SMEM 81920

// Fragment-ordered B image: [ch][ks][wn] blobs of 2560B, each [lane][20 uint32].
// uint32 (s,half): packed bf16 pair W[k0][n],W[k0+1][n], k0 = ks*16 + half*8 + 2q, n = ch*160+wn*80+8s+g.
#define NBLOB (2*19*2)
__device__ __align__(16) uint32_t g_Wfrag[NBLOB * 32 * 20];
__device__ float g_A[Ln * Bn];
__device__ float g_C[Ln * Bn];

__device__ __forceinline__ uint32_t smem_to_u32(const void* p) {
    uint32_t a;
    asm("{ .reg .u64 t; cvta.to.shared.u64 t, %1; cvt.u32.u64 %0, t; }" : "=r"(a) : "l"(p));
    return a;
}

#define LDSM_X4(r, addr)                                                        \
    asm volatile("ldmatrix.sync.aligned.m8n8.x4.shared.b16 {%0,%1,%2,%3}, [%4];"\
        : "=r"((r)[0]),"=r"((r)[1]),"=r"((r)[2]),"=r"((r)[3]) : "r"(addr))
#define MMA16816(d, a, b0, b1)                                                  \
    asm volatile("mma.sync.aligned.m16n8k16.row.col.f32.bf16.bf16.f32 "         \
        "{%0,%1,%2,%3}, {%4,%5,%6,%7}, {%8,%9}, {%0,%1,%2,%3};"                 \
        : "+f"((d)[0]),"+f"((d)[1]),"+f"((d)[2]),"+f"((d)[3])                   \
        : "r"((a)[0]),"r"((a)[1]),"r"((a)[2]),"r"((a)[3]), "r"(b0),"r"(b1))

// ============ kernel 1: build fragment-ordered bf16 Ws image ============
__global__ void prepW_kernel(const float* __restrict__ W) {
    int idx = blockIdx.x * 256 + threadIdx.x;
    if (idx >= NBLOB * 32 * 20) return;
    int su   = idx % 20;
    int lane = (idx / 20) & 31;
    int blob = idx / (32 * 20);
    int wn = blob & 1, ks = (blob >> 1) % 19, ch = blob / 38;
    int s = su >> 1, half = su & 1;
    int g = lane >> 2, q = lane & 3;
    int n  = ch * 160 + wn * 80 + 8 * s + g;
    int k0 = ks * 16 + half * 8 + 2 * q;
    float v0 = 0.f, v1 = 0.f;
    if (n < Dn) {
        if (k0 < Dn)     v0 = W[k0 * Dn + n] + W[n * Dn + k0];
        if (k0 + 1 < Dn) v1 = W[(k0 + 1) * Dn + n] + W[n * Dn + k0 + 1];
    }
    __nv_bfloat162 p = __floats2bfloat162_rn(v0, v1);
    g_Wfrag[idx] = *(uint32_t*)&p;
}

// ============ kernel 2: HMMA GEMM (B fragments from L2) + fused score dots ============
__global__ __launch_bounds__(256, 2) void score_kernel(const float* __restrict__ S) {
    extern __shared__ __align__(16) char smem[];
    const uint32_t sb = smem_to_u32(smem);
    const int tid  = threadIdx.x;
    const int lane = tid & 31;
    const int wid  = tid >> 5;
    const int wm   = wid & 3;            // 32-row slice
    const int wn   = wid >> 2;           // 80-col slice within chunk
    const int r0   = 32 * wm;
    const int g    = lane >> 2, q = lane & 3;
    const int  tile = blockIdx.x;
    const size_t m0 = (size_t)tile * 128;
    const bool hasPrev = (tile >= 32);

    // ---- stage X tile: 128 rows x 300 fp32 -> bf16 (cols 300..311 zero) ----
    const float* Sl = S + m0 * Dn;
    for (int idx = tid; idx < 128 * 75; idx += 256) {
        int r = idx / 75, f = idx % 75;
        float4 v = __ldg((const float4*)(Sl + (size_t)r * Dn) + f);
        __nv_bfloat162 p0 = __floats2bfloat162_rn(v.x, v.y);
        __nv_bfloat162 p1 = __floats2bfloat162_rn(v.z, v.w);
        *(uint2*)(smem + SM_X + r * XROW + f * 8) =
            make_uint2(*(uint32_t*)&p0, *(uint32_t*)&p1);
    }
    for (int idx = tid; idx < 128 * 3; idx += 256) {
        int r = idx / 3, w = idx % 3;
        *(uint2*)(smem + SM_X + r * XROW + 600 + w * 8) = make_uint2(0u, 0u);
    }
    __syncthreads();

    const uint32_t aBase0 = sb + SM_X + (r0 + (lane & 15)) * XROW + (lane >> 4) * 16;
    const uint32_t aBase1 = aBase0 + 16 * XROW;

    float aA[2][2] = {{0.f,0.f},{0.f,0.f}};
    float cA[2][2] = {{0.f,0.f},{0.f,0.f}};

    #pragma unroll
    for (int ch = 0; ch < 2; ch++) {
        // lane's fragment stream for this (ch, wn): 80B per k-step blob-pair
        const uint4* bp = (const uint4*)(g_Wfrag + ((size_t)(ch * 19 * 2 + wn) * 32 + lane) * 20);

        float acc[2][10][4];
        #pragma unroll
        for (int t = 0; t < 2; t++)
            #pragma unroll
            for (int s = 0; s < 10; s++)
                #pragma unroll
                for (int i = 0; i < 4; i++) acc[t][s][i] = 0.f;

        #pragma unroll 1
        for (int ks = 0; ks < 19; ks++) {
            uint32_t a0[4], a1[4];
            LDSM_X4(a0, aBase0 + ks * 32);
            LDSM_X4(a1, aBase1 + ks * 32);
            // 5 coalesced LDG.128 per lane -> 20 uint32 of B fragments
            uint4 bv[5];
            #pragma unroll
            for (int j = 0; j < 5; j++) bv[j] = __ldg(bp + j);
            bp += (size_t)(2 * 32 * 20) / 4;          // next ks (stride 5120B)
            const uint32_t* bw = (const uint32_t*)bv;
            #pragma unroll
            for (int s = 0; s < 10; s++) {
                MMA16816(acc[0][s], a0, bw[2 * s], bw[2 * s + 1]);
                MMA16816(acc[1][s], a1, bw[2 * s], bw[2 * s + 1]);
            }
        }

        // ---- dot epilogue: self from X smem, prev from gmem (L2-hot) ----
        #pragma unroll
        for (int t = 0; t < 2; t++) {
            const int rowA = r0 + 16 * t + g;
            const int rowB = rowA + 8;
            const float* pA = S + (m0 + rowA - (size_t)Bn) * Dn;
            const float* pB = S + (m0 + rowB - (size_t)Bn) * Dn;
            #pragma unroll
            for (int s = 0; s < 10; s++) {
                const int colg = ch * 160 + 80 * wn + 8 * s + 2 * q;
                if (colg < 304) {        // beyond: acc==0 but smem unstaged (NaN x 0 = NaN)
                    uint32_t svA = *(const uint32_t*)(smem + SM_X + rowA * XROW + colg * 2);
                    uint32_t svB = *(const uint32_t*)(smem + SM_X + rowB * XROW + colg * 2);
                    __nv_bfloat162 sA2 = *(__nv_bfloat162*)&svA;
                    __nv_bfloat162 sB2 = *(__nv_bfloat162*)&svB;
                    aA[t][0] = fmaf(__bfloat162float(sA2.x), acc[t][s][0],
                               fmaf(__bfloat162float(sA2.y), acc[t][s][1], aA[t][0]));
                    aA[t][1] = fmaf(__bfloat162float(sB2.x), acc[t][s][2],
                               fmaf(__bfloat162float(sB2.y), acc[t][s][3], aA[t][1]));
                    if (hasPrev && colg < Dn) {
                        float2 pvA = __ldg((const float2*)(pA + colg));
                        float2 pvB = __ldg((const float2*)(pB + colg));
                        cA[t][0] = fmaf(pvA.x, acc[t][s][0], fmaf(pvA.y, acc[t][s][1], cA[t][0]));
                        cA[t][1] = fmaf(pvB.x, acc[t][s][2], fmaf(pvB.y, acc[t][s][3], cA[t][1]));
                    }
                }
            }
        }
    }

    // ---- final reduce: q lanes, then the 2 n-warps via smem ----
    float* sRA = (float*)(smem + SM_RA);
    float* sRC = (float*)(smem + SM_RC);
    #pragma unroll
    for (int t = 0; t < 2; t++)
        #pragma unroll
        for (int h = 0; h < 2; h++) {
            float a = aA[t][h], c = cA[t][h];
            a += __shfl_xor_sync(0xffffffffu, a, 1);
            a += __shfl_xor_sync(0xffffffffu, a, 2);
            c += __shfl_xor_sync(0xffffffffu, c, 1);
            c += __shfl_xor_sync(0xffffffffu, c, 2);
            if (q == 0) {
                int row = r0 + 16 * t + 8 * h + g;
                sRA[wn * 128 + row] = a;
                sRC[wn * 128 + row] = c;
            }
        }
    __syncthreads();
    if (tid < 128) {
        g_A[m0 + tid] = 0.5f * (sRA[tid] + sRA[128 + tid]);
        if (hasPrev) g_C[m0 + tid] = 0.5f * (sRC[tid] + sRC[128 + tid]);
    }
}

// ============ kernel 3: l-streaming blend, 2 warps per b-row ============
// Warp-half hw owns float4 columns [hw*38, hw*38+37] (37 for hw=1); 3-row register ring.
__global__ __launch_bounds__(256) void blend_kernel(const float* __restrict__ S,
                                                    const int* __restrict__ sizes,
                                                    float* __restrict__ out) {
    const int warp = threadIdx.x >> 5;
    const int lane = threadIdx.x & 31;
    const int b    = blockIdx.x * 4 + (warp >> 1);
    const int hw   = warp & 1;
    const int sz   = sizes[b];
    const float inv_d = 1.0f / 300.0f;

    const int lo = hw * 38;            // 38 f4 for hw=0, 37 for hw=1
    const int hi = hw ? 75 : 38;
    bool val[2];
    int  col[2];
    #pragma unroll
    for (int j = 0; j < 2; j++) {
        col[j] = lo + j * 32 + lane;
        val[j] = col[j] < hi;
    }

    const size_t slabF4 = (size_t)Bn * Dn / 4;        // 307200
    const float4* rp = (const float4*)(S + (size_t)b * Dn);
    float4*       op = (float4*)(out + (size_t)b * Dn);

    const float4 z = make_float4(0.f, 0.f, 0.f, 0.f);
    float4 prv[2] = {z, z}, cur[2], nxt[2];
    #pragma unroll
    for (int j = 0; j < 2; j++) cur[j] = val[j] ? __ldg(rp + col[j]) : z;

    for (int l = 0; l < Ln; ++l) {
        const bool hasN = (l < Ln - 1);
        #pragma unroll
        for (int j = 0; j < 2; j++)
            nxt[j] = (hasN && val[j]) ? __ldg(rp + slabF4 + col[j]) : z;

        float l1 = g_A[l * Bn + b] * inv_d;
        float l0 = (l >= 1 && l < sz)     ? g_C[l * Bn + b] * inv_d       : -INFINITY;
        float l2 = (hasN && l < sz - 1)   ? g_C[(l + 1) * Bn + b] * inv_d : -INFINITY;

        float mx = fmaxf(l1, fmaxf(l0, l2));
        float e0 = expf(l0 - mx), e1 = expf(l1 - mx), e2 = expf(l2 - mx);
        float inv = 1.0f / (e0 + e1 + e2);
        float w0 = e0 * inv, w1 = e1 * inv, w2 = e2 * inv;

        #pragma unroll
        for (int j = 0; j < 2; j++) {
            if (val[j]) {
                float4 r;
                r.x = w1 * cur[j].x + w0 * prv[j].x + w2 * nxt[j].x;
                r.y = w1 * cur[j].y + w0 * prv[j].y + w2 * nxt[j].y;
                r.z = w1 * cur[j].z + w0 * prv[j].z + w2 * nxt[j].z;
                r.w = w1 * cur[j].w + w0 * prv[j].w + w2 * nxt[j].w;
                op[col[j]] = r;
            }
        }
        #pragma unroll
        for (int j = 0; j < 2; j++) { prv[j] = cur[j]; cur[j] = nxt[j]; }
        rp += slabF4;
        op += slabF4;
    }
}

// ==================== launch ====================
extern "C" void kernel_launch(void* const* d_in, const int* in_sizes, int n_in,
                              void* d_out, int out_size) {
    const float* S     = (const float*)d_in[0];
    const int*   sizes = (const int*)d_in[1];
    const float* W     = (const float*)d_in[2];
    float*       out   = (float*)d_out;
    (void)in_sizes; (void)n_in; (void)out_size;

    prepW_kernel<<<(NBLOB * 32 * 20 + 255) / 256, 256>>>(W);

    cudaFuncSetAttribute(score_kernel, cudaFuncAttributeMaxDynamicSharedMemorySize, DYN_SMEM);
    score_kernel<<<4096, 256, DYN_SMEM>>>(S);

    blend_kernel<<<Bn / 4, 256>>>(S, sizes, out);
}

// round 13
// speedup vs baseline: 1.1352x; 1.1352x over previous
#include <cuda_runtime.h>
#include <cuda_bf16.h>
#include <math.h>
#include <stdint.h>

#define Ln 128
#define Bn 4096
#define Dn 300
#define XROW 624                // 304 bf16 + 16B pad
#define SM_X  0
#define SM_RA 79872             // 128*624
#define SM_RC 80896
#define DYN_SMEM 81920

// Fragment-ordered B image: blob (ch,ks,wn) of [lane][20 u32] (ch1 uses 18 + 2 pad).
// blob index = ch*38 + ks*2 + wn; per-ks stride = 2 blobs = 1280 u32.
// ch0: n = wn*80 + 8s + g (s<10); ch1: n = 160 + wn*72 + 8s + g (s<9). k0 = ks*16 + half*8 + 2q.
#define NBLOB (2*19*2)
__device__ __align__(16) uint32_t g_Wfrag[NBLOB * 32 * 20];
__device__ float g_A[Ln * Bn];
__device__ float g_C[Ln * Bn];

__device__ __forceinline__ uint32_t smem_to_u32(const void* p) {
    uint32_t a;
    asm("{ .reg .u64 t; cvta.to.shared.u64 t, %1; cvt.u32.u64 %0, t; }" : "=r"(a) : "l"(p));
    return a;
}

#define LDSM_X4(r, addr)                                                        \
    asm volatile("ldmatrix.sync.aligned.m8n8.x4.shared.b16 {%0,%1,%2,%3}, [%4];"\
        : "=r"((r)[0]),"=r"((r)[1]),"=r"((r)[2]),"=r"((r)[3]) : "r"(addr))
#define MMA16816(d, a, b0, b1)                                                  \
    asm volatile("mma.sync.aligned.m16n8k16.row.col.f32.bf16.bf16.f32 "         \
        "{%0,%1,%2,%3}, {%4,%5,%6,%7}, {%8,%9}, {%0,%1,%2,%3};"                 \
        : "+f"((d)[0]),"+f"((d)[1]),"+f"((d)[2]),"+f"((d)[3])                   \
        : "r"((a)[0]),"r"((a)[1]),"r"((a)[2]),"r"((a)[3]), "r"(b0),"r"(b1))

// ============ kernel 1: build fragment-ordered bf16 Ws image ============
__global__ void prepW_kernel(const float* __restrict__ W) {
    int idx = blockIdx.x * 256 + threadIdx.x;
    if (idx >= NBLOB * 32 * 20) return;
    int su   = idx % 20;
    int lane = (idx / 20) & 31;
    int blob = idx / (32 * 20);
    int wn = blob & 1, ks = (blob >> 1) % 19, ch = blob / 38;
    int g = lane >> 2, q = lane & 3;
    uint32_t pk = 0u;
    const int nsu = ch ? 18 : 20;        // valid u32 per lane: ch1 has 9 s-tiles
    if (su < nsu) {
        int s = su >> 1, half = su & 1;
        int n  = ch ? (160 + wn * 72 + 8 * s + g) : (wn * 80 + 8 * s + g);
        int k0 = ks * 16 + half * 8 + 2 * q;
        float v0 = 0.f, v1 = 0.f;
        if (n < Dn) {
            if (k0 < Dn)     v0 = W[k0 * Dn + n] + W[n * Dn + k0];
            if (k0 + 1 < Dn) v1 = W[(k0 + 1) * Dn + n] + W[n * Dn + k0 + 1];
        }
        __nv_bfloat162 p = __floats2bfloat162_rn(v0, v1);
        pk = *(uint32_t*)&p;
    }
    g_Wfrag[idx] = pk;
}

// ---------------- templated chunk body (k-loop + dot epilogue) ----------------
template <int NS>
__device__ __forceinline__ void run_chunk(
    const char* smemc, uint32_t aBase0, uint32_t aBase1,
    const uint32_t* bp, int colBase,
    const float* __restrict__ S, size_t m0, bool hasPrev,
    int r0, int g, int q, float (&aA)[2][2], float (&cA)[2][2])
{
    float acc[2][NS][4];
    #pragma unroll
    for (int t = 0; t < 2; t++)
        #pragma unroll
        for (int s = 0; s < NS; s++)
            #pragma unroll
            for (int i = 0; i < 4; i++) acc[t][s][i] = 0.f;

    #pragma unroll 1
    for (int ks = 0; ks < 19; ks++) {
        uint32_t a0[4], a1[4];
        LDSM_X4(a0, aBase0 + ks * 32);
        LDSM_X4(a1, aBase1 + ks * 32);
        uint32_t bw[2 * NS];
        #pragma unroll
        for (int j = 0; j < NS / 2; j++) {
            uint4 v = __ldg((const uint4*)bp + j);
            bw[4 * j] = v.x; bw[4 * j + 1] = v.y; bw[4 * j + 2] = v.z; bw[4 * j + 3] = v.w;
        }
        if constexpr (NS & 1) {
            uint2 v = __ldg((const uint2*)(bp + 4 * (NS / 2)));
            bw[2 * NS - 2] = v.x; bw[2 * NS - 1] = v.y;
        }
        bp += 2 * 32 * 20;               // next ks (stride 5120B)
        #pragma unroll
        for (int s = 0; s < NS; s++) {
            MMA16816(acc[0][s], a0, bw[2 * s], bw[2 * s + 1]);
            MMA16816(acc[1][s], a1, bw[2 * s], bw[2 * s + 1]);
        }
    }

    // dot epilogue: self from X smem, prev from gmem (L2-hot)
    #pragma unroll
    for (int t = 0; t < 2; t++) {
        const int rowA = r0 + 16 * t + g;
        const int rowB = rowA + 8;
        const float* pA = S + (m0 + rowA - (size_t)Bn) * Dn;
        const float* pB = S + (m0 + rowB - (size_t)Bn) * Dn;
        #pragma unroll
        for (int s = 0; s < NS; s++) {
            const int colg = colBase + 8 * s + 2 * q;   // always < 304
            uint32_t svA = *(const uint32_t*)(smemc + SM_X + rowA * XROW + colg * 2);
            uint32_t svB = *(const uint32_t*)(smemc + SM_X + rowB * XROW + colg * 2);
            __nv_bfloat162 sA2 = *(__nv_bfloat162*)&svA;
            __nv_bfloat162 sB2 = *(__nv_bfloat162*)&svB;
            aA[t][0] = fmaf(__bfloat162float(sA2.x), acc[t][s][0],
                       fmaf(__bfloat162float(sA2.y), acc[t][s][1], aA[t][0]));
            aA[t][1] = fmaf(__bfloat162float(sB2.x), acc[t][s][2],
                       fmaf(__bfloat162float(sB2.y), acc[t][s][3], aA[t][1]));
            if (hasPrev && colg < Dn) {
                float2 pvA = __ldg((const float2*)(pA + colg));
                float2 pvB = __ldg((const float2*)(pB + colg));
                cA[t][0] = fmaf(pvA.x, acc[t][s][0], fmaf(pvA.y, acc[t][s][1], cA[t][0]));
                cA[t][1] = fmaf(pvB.x, acc[t][s][2], fmaf(pvB.y, acc[t][s][3], cA[t][1]));
            }
        }
    }
}

// ============ kernel 2: HMMA GEMM (B fragments from L2) + fused score dots ============
__global__ __launch_bounds__(256, 2) void score_kernel(const float* __restrict__ S) {
    extern __shared__ __align__(16) char smem[];
    const uint32_t sb = smem_to_u32(smem);
    const int tid  = threadIdx.x;
    const int lane = tid & 31;
    const int wid  = tid >> 5;
    const int wm   = wid & 3;            // 32-row slice
    const int wn   = wid >> 2;           // n-slice within chunk
    const int r0   = 32 * wm;
    const int g    = lane >> 2, q = lane & 3;
    const int  tile = blockIdx.x;
    const size_t m0 = (size_t)tile * 128;
    const bool hasPrev = (tile >= 32);

    // ---- stage X tile: 128 rows x 300 fp32 -> bf16 (cols 300..311 zero) ----
    const float* Sl = S + m0 * Dn;
    for (int idx = tid; idx < 128 * 75; idx += 256) {
        int r = idx / 75, f = idx % 75;
        float4 v = __ldg((const float4*)(Sl + (size_t)r * Dn) + f);
        __nv_bfloat162 p0 = __floats2bfloat162_rn(v.x, v.y);
        __nv_bfloat162 p1 = __floats2bfloat162_rn(v.z, v.w);
        *(uint2*)(smem + SM_X + r * XROW + f * 8) =
            make_uint2(*(uint32_t*)&p0, *(uint32_t*)&p1);
    }
    for (int idx = tid; idx < 128 * 3; idx += 256) {
        int r = idx / 3, w = idx % 3;
        *(uint2*)(smem + SM_X + r * XROW + 600 + w * 8) = make_uint2(0u, 0u);
    }
    __syncthreads();

    const uint32_t aBase0 = sb + SM_X + (r0 + (lane & 15)) * XROW + (lane >> 4) * 16;
    const uint32_t aBase1 = aBase0 + 16 * XROW;

    float aA[2][2] = {{0.f,0.f},{0.f,0.f}};
    float cA[2][2] = {{0.f,0.f},{0.f,0.f}};

    // chunk 0: 160 cols (10 s-tiles), chunk 1: 144 cols (9 s-tiles)
    {
        const uint32_t* bp0 = g_Wfrag + ((size_t)(0 * 38 + wn) * 32 + lane) * 20;
        run_chunk<10>((const char*)smem, aBase0, aBase1, bp0, 80 * wn,
                      S, m0, hasPrev, r0, g, q, aA, cA);
    }
    {
        const uint32_t* bp1 = g_Wfrag + ((size_t)(1 * 38 + wn) * 32 + lane) * 20;
        run_chunk<9>((const char*)smem, aBase0, aBase1, bp1, 160 + 72 * wn,
                     S, m0, hasPrev, r0, g, q, aA, cA);
    }

    // ---- final reduce: q lanes, then the 2 n-warps via smem ----
    float* sRA = (float*)(smem + SM_RA);
    float* sRC = (float*)(smem + SM_RC);
    #pragma unroll
    for (int t = 0; t < 2; t++)
        #pragma unroll
        for (int h = 0; h < 2; h++) {
            float a = aA[t][h], c = cA[t][h];
            a += __shfl_xor_sync(0xffffffffu, a, 1);
            a += __shfl_xor_sync(0xffffffffu, a, 2);
            c += __shfl_xor_sync(0xffffffffu, c, 1);
            c += __shfl_xor_sync(0xffffffffu, c, 2);
            if (q == 0) {
                int row = r0 + 16 * t + 8 * h + g;
                sRA[wn * 128 + row] = a;
                sRC[wn * 128 + row] = c;
            }
        }
    __syncthreads();
    if (tid < 128) {
        g_A[m0 + tid] = 0.5f * (sRA[tid] + sRA[128 + tid]);
        if (hasPrev) g_C[m0 + tid] = 0.5f * (sRC[tid] + sRC[128 + tid]);
    }
}

// ============ kernel 3: l-streaming blend (R9 version, untouched) ============
__global__ __launch_bounds__(256) void blend_kernel(const float* __restrict__ S,
                                                    const int* __restrict__ sizes,
                                                    float* __restrict__ out) {
    const int warp = threadIdx.x >> 5;
    const int lane = threadIdx.x & 31;
    const int b    = blockIdx.x * 8 + warp;
    const int sz   = sizes[b];
    const float inv_d = 1.0f / 300.0f;

    bool val[3];
    #pragma unroll
    for (int j = 0; j < 3; j++) val[j] = (j * 32 + lane) < 75;

    const size_t slabF4 = (size_t)Bn * Dn / 4;        // 307200
    const float4* rp = (const float4*)(S + (size_t)b * Dn);
    float4*       op = (float4*)(out + (size_t)b * Dn);

    const float4 z = make_float4(0.f, 0.f, 0.f, 0.f);
    float4 prv[3] = {z, z, z}, cur[3], nxt[3];
    #pragma unroll
    for (int j = 0; j < 3; j++) cur[j] = val[j] ? __ldg(rp + j * 32 + lane) : z;

    for (int l = 0; l < Ln; ++l) {
        const bool hasN = (l < Ln - 1);
        #pragma unroll
        for (int j = 0; j < 3; j++)
            nxt[j] = (hasN && val[j]) ? __ldg(rp + slabF4 + j * 32 + lane) : z;

        float l1 = g_A[l * Bn + b] * inv_d;
        float l0 = (l >= 1 && l < sz)     ? g_C[l * Bn + b] * inv_d       : -INFINITY;
        float l2 = (hasN && l < sz - 1)   ? g_C[(l + 1) * Bn + b] * inv_d : -INFINITY;

        float mx = fmaxf(l1, fmaxf(l0, l2));
        float e0 = expf(l0 - mx), e1 = expf(l1 - mx), e2 = expf(l2 - mx);
        float inv = 1.0f / (e0 + e1 + e2);
        float w0 = e0 * inv, w1 = e1 * inv, w2 = e2 * inv;

        #pragma unroll
        for (int j = 0; j < 3; j++) {
            if (val[j]) {
                float4 r;
                r.x = w1 * cur[j].x + w0 * prv[j].x + w2 * nxt[j].x;
                r.y = w1 * cur[j].y + w0 * prv[j].y + w2 * nxt[j].y;
                r.z = w1 * cur[j].z + w0 * prv[j].z + w2 * nxt[j].z;
                r.w = w1 * cur[j].w + w0 * prv[j].w + w2 * nxt[j].w;
                op[j * 32 + lane] = r;
            }
        }
        #pragma unroll
        for (int j = 0; j < 3; j++) { prv[j] = cur[j]; cur[j] = nxt[j]; }
        rp += slabF4;
        op += slabF4;
    }
}

// ==================== launch ====================
extern "C" void kernel_launch(void* const* d_in, const int* in_sizes, int n_in,
                              void* d_out, int out_size) {
    const float* S     = (const float*)d_in[0];
    const int*   sizes = (const int*)d_in[1];
    const float* W     = (const float*)d_in[2];
    float*       out   = (float*)d_out;
    (void)in_sizes; (void)n_in; (void)out_size;

    prepW_kernel<<<(NBLOB * 32 * 20 + 255) / 256, 256>>>(W);

    cudaFuncSetAttribute(score_kernel, cudaFuncAttributeMaxDynamicSharedMemorySize, DYN_SMEM);
    score_kernel<<<4096, 256, DYN_SMEM>>>(S);

    blend_kernel<<<Bn / 8, 256>>>(S, sizes, out);
}